// round 11
// baseline (speedup 1.0000x reference)
#include <cuda_runtime.h>
#include <cuda_bf16.h>

// GAT: 4 GATConv layers (3 heads x 12 out), concat for layers 0-2 (relu), mean
// for layer 3, then two small linear layers -> [N, 6].
//
//  1) CSR build, atomic-free scatter: hist records each edge's intra-node RANK
//     (atomic return value); scatter pos = rowstart[d] + rank. Self-loop at
//     rowstart[n+1]-1.
//  2) Per layer: node transform (smem-staged, 2-node register blocking), then
//     FEATURE-PER-LANE warp aggregation, 1 node per warp; h rows padded to 40
//     floats (160B, sector-aligned gathers). Softmax max-subtraction dropped:
//     exact (every segment has a self-loop, logits O(1)).
//  3) Standalone fused lin1+lin2 -> d_out.

#define HEADS 3
#define OUTF  12
#define F     36            // HEADS*OUTF
#define HPAD  40            // padded h row stride (160B, sector aligned)
#define NMAX  50000
#define EMAX  800000
#define TOTMAX (EMAX + NMAX)

// ---------------- device scratch (static; no allocation) ----------------
__device__ float g_y[NMAX * F];     // layer activations (holds [N,12] after layer 3)
__device__ float g_h[NMAX * HPAD];  // transformed features (padded rows)
__device__ float g_als[NMAX * HEADS];
__device__ float g_ald[NMAX * HEADS];
__device__ int   g_deg[NMAX];       // zero at entry (zero-init / reset each pass)
__device__ int   g_rank[EMAX];      // intra-node rank of each edge
__device__ int   g_rowstart[NMAX + 1];
__device__ int   g_csrsrc[TOTMAX + 32];   // +32 pad (zero-init) for chunked over-read
__device__ int   g_blocksums[128];

// ---------------- CSR build ----------------
__global__ void k_hist(const int* __restrict__ dst, int E) {
    int base = blockIdx.x * 1024 + threadIdx.x;
    #pragma unroll
    for (int k = 0; k < 4; k++) {
        int i = base + k * 256;
        if (i < E) g_rank[i] = atomicAdd(&g_deg[dst[i]], 1);
    }
}

__global__ void k_scan_block(int N) {  // blockDim == 1024
    __shared__ int sh[1024];
    int t = threadIdx.x;
    int idx = blockIdx.x * 1024 + t;
    int v = (idx < N) ? (g_deg[idx] + 1) : 0;   // +1 = self-loop
    sh[t] = v;
    __syncthreads();
    #pragma unroll
    for (int off = 1; off < 1024; off <<= 1) {
        int add = (t >= off) ? sh[t - off] : 0;
        __syncthreads();
        sh[t] += add;
        __syncthreads();
    }
    if (idx < N) g_rowstart[idx] = sh[t];          // per-block inclusive (temp)
    if (t == 1023) g_blocksums[blockIdx.x] = sh[1023];
}

// Fused: every block redundantly scans the (<=128) block sums in smem, then
// converts to exclusive row starts and RESETS g_deg for the next replay.
__global__ void k_scan_finish(int N, int TOT, int nb) {
    __shared__ int soff[128];
    int t = threadIdx.x;    // blockDim == 256
    if (t < 128) soff[t] = (t < nb) ? g_blocksums[t] : 0;
    __syncthreads();
    #pragma unroll
    for (int off = 1; off < 128; off <<= 1) {
        int add = 0;
        if (t < 128 && t >= off) add = soff[t - off];
        __syncthreads();
        if (t < 128) soff[t] += add;
        __syncthreads();
    }
    int idx = blockIdx.x * blockDim.x + t;
    if (idx < N) {
        int b = idx >> 10;
        int boff = (b == 0) ? 0 : soff[b - 1];
        int incl = g_rowstart[idx] + boff;
        g_rowstart[idx] = incl - (g_deg[idx] + 1);
        g_deg[idx] = 0;       // reset for next replay
    }
    if (idx == 0) g_rowstart[N] = TOT;
}

// Atomic-free scatter: pos = rowstart[d] + rank; self-loop at rowstart[n+1]-1.
__global__ void k_scatter(const int* __restrict__ src, const int* __restrict__ dst,
                          int E, int N) {
    int base = blockIdx.x * 1024 + threadIdx.x;
    #pragma unroll
    for (int k = 0; k < 4; k++) {
        int i = base + k * 256;
        if (i < E) {
            int d = dst[i];
            g_csrsrc[g_rowstart[d] + g_rank[i]] = src[i];
        } else if (i < E + N) {
            int n = i - E;
            g_csrsrc[g_rowstart[n + 1] - 1] = n;  // self loop
        }
    }
}

// ---------------- node transform: h = y @ W^T, attention logits ----------------
// Block = 128 threads handling 256 nodes (2 per thread). Rows staged coalesced
// into padded smem (stride 37, odd -> conflict-free); h written back through
// the same rows and stored to stride-HPAD gmem rows.
template <int IN, bool FROMX>
__global__ void __launch_bounds__(128) k_node_transform(
        const float* __restrict__ xin,
        const float* __restrict__ W,
        const float* __restrict__ asrc,
        const float* __restrict__ adst, int N) {
    __shared__ float sW[F * F];
    __shared__ float sA[F], sB[F];
    __shared__ float sy[256 * 37];
    int t = threadIdx.x;
    for (int i = t; i < F * IN; i += 128) sW[i] = W[i];
    if (t < F) { sA[t] = asrc[t]; sB[t] = adst[t]; }

    int n0 = blockIdx.x * 256;
    int rows = min(256, N - n0);
    const float* srcbase = FROMX ? (xin + (size_t)n0 * IN) : (g_y + (size_t)n0 * IN);
    int avail = rows * IN;
    for (int idx = t; idx < avail; idx += 128) {
        int r = idx / IN, c = idx - r * IN;
        sy[r * 37 + c] = srcbase[idx];
    }
    __syncthreads();

    bool va = (t < rows);
    bool vb = (t + 128 < rows);
    int na = n0 + t, nb2 = n0 + t + 128;
    float ya[IN], yb[IN];
    #pragma unroll
    for (int i = 0; i < IN; i++) ya[i] = va ? sy[t * 37 + i] : 0.f;
    #pragma unroll
    for (int i = 0; i < IN; i++) yb[i] = vb ? sy[(t + 128) * 37 + i] : 0.f;

    float asa[3] = {0.f, 0.f, 0.f}, ada[3] = {0.f, 0.f, 0.f};
    float asb[3] = {0.f, 0.f, 0.f}, adb[3] = {0.f, 0.f, 0.f};

    #pragma unroll
    for (int j = 0; j < F; j++) {
        float ha = 0.f, hb = 0.f;
        #pragma unroll
        for (int i = 0; i < IN; i++) {
            float w = sW[j * IN + i];
            ha += w * ya[i];
            hb += w * yb[i];
        }
        sy[t * 37 + j] = ha;            // own row: no cross-thread hazard
        sy[(t + 128) * 37 + j] = hb;
        float aj = sA[j], bj = sB[j];
        int hh = j / OUTF;
        asa[hh] += ha * aj; ada[hh] += ha * bj;
        asb[hh] += hb * aj; adb[hh] += hb * bj;
    }
    if (va) {
        #pragma unroll
        for (int hh = 0; hh < 3; hh++) {
            g_als[na * 3 + hh] = asa[hh];
            g_ald[na * 3 + hh] = ada[hh];
        }
    }
    if (vb) {
        #pragma unroll
        for (int hh = 0; hh < 3; hh++) {
            g_als[nb2 * 3 + hh] = asb[hh];
            g_ald[nb2 * 3 + hh] = adb[hh];
        }
    }
    __syncthreads();
    int availh = rows * F;
    float* hbase = g_h + (size_t)n0 * HPAD;
    for (int idx = t; idx < availh; idx += 128) {
        int r = idx / F, c = idx - r * F;
        hbase[r * HPAD + c] = sy[r * 37 + c];
    }
}

// ---------------- aggregation: warp per node, FEATURE per lane ----------------
// Lane f (0..31) owns feature f; lanes 24..27 additionally own features 32..35
// (same head 2 -> reuse own p and sp; no per-edge shuffle). The softmax
// denominator is accumulated identically by every lane of a head group.
template <bool CONCAT>
__global__ void k_gat_aggregate(const float* __restrict__ bias, int N) {
    int warp = (blockIdx.x * blockDim.x + threadIdx.x) >> 5;
    int lane = threadIdx.x & 31;
    if (warp >= N) return;
    int n = warp;
    int r0 = g_rowstart[n];
    int r1 = g_rowstart[n + 1];

    int h1 = lane / OUTF;          // 0,1,2
    float ald1 = g_ald[n * 3 + h1];
    bool sec = (lane >= 24) && (lane < 28);

    float acc1 = 0.f, acc2 = 0.f, sp1 = 0.f;

    for (int base = r0; base < r1; base += 32) {
        int mysrc = g_csrsrc[base + lane];   // chunk preload (zero-padded tail)
        int cnt = min(32, r1 - base);
        #pragma unroll 4
        for (int j = 0; j < cnt; j++) {
            int s = __shfl_sync(0xFFFFFFFFu, mysrc, j);
            float e = g_als[s * 3 + h1] + ald1;
            e = fmaxf(e, 0.2f * e);          // leaky relu (slope < 1)
            float p = __expf(e);
            sp1 += p;
            const float* hr = g_h + (size_t)s * HPAD;
            acc1 += p * hr[lane];
            if (sec) acc2 += p * hr[32 + (lane - 24)];
        }
    }

    float inv1 = 1.f / (sp1 + 1e-16f);

    if (CONCAT) {
        float v = acc1 * inv1 + bias[lane];
        g_y[(size_t)n * F + lane] = fmaxf(v, 0.f);
        if (sec) {
            float v2 = acc2 * inv1 + bias[32 + (lane - 24)];
            g_y[(size_t)n * F + 32 + (lane - 24)] = fmaxf(v2, 0.f);
        }
    } else {
        // mean over heads
        float v1 = acc1 * inv1;              // (head h1, feat lane%12)
        float v2 = acc2 * inv1;              // lanes 24..27: head2 feats 8..11
        float b12 = __shfl_sync(0xFFFFFFFFu, v1, lane + 12);           // head1
        float c24 = __shfl_sync(0xFFFFFFFFu, v1, lane + 24);           // head2 o<8
        float c2  = __shfl_sync(0xFFFFFFFFu, v2, lane + 16);           // head2 o>=8
        if (lane < OUTF) {
            float c = (lane < 8) ? c24 : c2;
            float v = (v1 + b12 + c) * (1.f / 3.f) + bias[lane];
            g_y[(size_t)n * OUTF + lane] = v;   // no relu on last GAT layer
        }
    }
}

// ---------------- final linears: [N,12] -> 12 -> 6 ----------------
__global__ void k_final_linear(const float* __restrict__ w1, const float* __restrict__ b1,
                               const float* __restrict__ w2, const float* __restrict__ b2,
                               float* __restrict__ out, int N) {
    __shared__ float sw1[144], sb1[12], sw2[72], sb2[6];
    int t = threadIdx.x;
    for (int i = t; i < 144; i += blockDim.x) sw1[i] = w1[i];
    for (int i = t; i < 72;  i += blockDim.x) sw2[i] = w2[i];
    if (t < 12) sb1[t] = b1[t];
    if (t < 6)  sb2[t] = b2[t];
    __syncthreads();
    int n = blockIdx.x * blockDim.x + t;
    if (n >= N) return;
    float v[12];
    const float4* vp = (const float4*)(g_y + (size_t)n * 12);
    #pragma unroll
    for (int q = 0; q < 3; q++) {
        float4 w = vp[q];
        v[q * 4 + 0] = w.x; v[q * 4 + 1] = w.y;
        v[q * 4 + 2] = w.z; v[q * 4 + 3] = w.w;
    }
    float u[12];
    #pragma unroll
    for (int j = 0; j < 12; j++) {
        float a = sb1[j];
        #pragma unroll
        for (int i = 0; i < 12; i++) a += v[i] * sw1[j * 12 + i];
        u[j] = a;
    }
    #pragma unroll
    for (int k = 0; k < 6; k++) {
        float a = sb2[k];
        #pragma unroll
        for (int j = 0; j < 12; j++) a += u[j] * sw2[k * 12 + j];
        out[(size_t)n * 6 + k] = a;
    }
}

// ---------------- launch ----------------
extern "C" void kernel_launch(void* const* d_in, const int* in_sizes, int n_in,
                              void* d_out, int out_size) {
    const float* x  = (const float*)d_in[0];
    const int*   ei = (const int*)d_in[1];
    int E = in_sizes[1] / 2;
    int N = in_sizes[0] / 24;
    if (N > NMAX || E > EMAX) return;
    const int* srcp = ei;
    const int* dstp = ei + E;

    const float* W[4], *AS[4], *AD[4], *B[4];
    for (int l = 0; l < 4; l++) {
        W[l]  = (const float*)d_in[2 + 4 * l];
        AS[l] = (const float*)d_in[3 + 4 * l];
        AD[l] = (const float*)d_in[4 + 4 * l];
        B[l]  = (const float*)d_in[5 + 4 * l];
    }
    const float* lin1w = (const float*)d_in[18];
    const float* lin1b = (const float*)d_in[19];
    const float* lin2w = (const float*)d_in[20];
    const float* lin2b = (const float*)d_in[21];
    float* out = (float*)d_out;

    int TOT = E + N;
    int nb = (N + 1023) / 1024;

    k_hist<<<(E + 1023) / 1024, 256>>>(dstp, E);
    k_scan_block<<<nb, 1024>>>(N);
    k_scan_finish<<<(N + 255) / 256, 256>>>(N, TOT, nb);
    k_scatter<<<(TOT + 1023) / 1024, 256>>>(srcp, dstp, E, N);

    int ngrid = (N + 255) / 256;             // 256 nodes per transform block
    int agrid = (N * 32 + 255) / 256;        // 1 node per warp

    // layer 0 (in=24, from x)
    k_node_transform<24, true><<<ngrid, 128>>>(x, W[0], AS[0], AD[0], N);
    k_gat_aggregate<true><<<agrid, 256>>>(B[0], N);
    // layer 1
    k_node_transform<36, false><<<ngrid, 128>>>(nullptr, W[1], AS[1], AD[1], N);
    k_gat_aggregate<true><<<agrid, 256>>>(B[1], N);
    // layer 2
    k_node_transform<36, false><<<ngrid, 128>>>(nullptr, W[2], AS[2], AD[2], N);
    k_gat_aggregate<true><<<agrid, 256>>>(B[2], N);
    // layer 3 (mean over heads, no relu)
    k_node_transform<36, false><<<ngrid, 128>>>(nullptr, W[3], AS[3], AD[3], N);
    k_gat_aggregate<false><<<agrid, 256>>>(B[3], N);

    k_final_linear<<<(N + 127) / 128, 128>>>(lin1w, lin1b, lin2w, lin2b, out, N);
}

// round 14
// speedup vs baseline: 1.5359x; 1.5359x over previous
#include <cuda_runtime.h>
#include <cuda_bf16.h>

// GAT: 4 GATConv layers (3 heads x 12 out), concat for layers 0-2 (relu), mean
// for layer 3, then two small linear layers -> [N, 6].
//
//  1) CSR build, atomic-free scatter: hist records each edge's intra-node RANK
//     (atomic return value); scatter pos = rowstart[d] + rank. Self-loop at
//     rowstart[n+1]-1.
//  2) Per layer: node transform (smem-staged, 2-node register blocking), then
//     FEATURE-PER-LANE warp aggregation, 1 node per warp, dense 36-float h
//     rows. Softmax max-subtraction dropped: exact (every segment has a
//     self-loop, logits O(1)).
//  3) Standalone fused lin1+lin2 -> d_out.

#define HEADS 3
#define OUTF  12
#define F     36            // HEADS*OUTF
#define NMAX  50000
#define EMAX  800000
#define TOTMAX (EMAX + NMAX)

// ---------------- device scratch (static; no allocation) ----------------
__device__ float g_y[NMAX * F];     // layer activations (holds [N,12] after layer 3)
__device__ float g_h[NMAX * F];     // transformed features (dense rows)
__device__ float g_als[NMAX * HEADS];
__device__ float g_ald[NMAX * HEADS];
__device__ int   g_deg[NMAX];       // zero at entry (zero-init / reset each pass)
__device__ int   g_rank[EMAX];      // intra-node rank of each edge
__device__ int   g_rowstart[NMAX + 1];
__device__ int   g_csrsrc[TOTMAX + 32];   // +32 pad (zero-init) for chunked over-read
__device__ int   g_blocksums[128];

// ---------------- CSR build ----------------
__global__ void k_hist(const int* __restrict__ dst, int E) {
    int base = blockIdx.x * 1024 + threadIdx.x;
    #pragma unroll
    for (int k = 0; k < 4; k++) {
        int i = base + k * 256;
        if (i < E) g_rank[i] = atomicAdd(&g_deg[dst[i]], 1);
    }
}

__global__ void k_scan_block(int N) {  // blockDim == 1024
    __shared__ int sh[1024];
    int t = threadIdx.x;
    int idx = blockIdx.x * 1024 + t;
    int v = (idx < N) ? (g_deg[idx] + 1) : 0;   // +1 = self-loop
    sh[t] = v;
    __syncthreads();
    #pragma unroll
    for (int off = 1; off < 1024; off <<= 1) {
        int add = (t >= off) ? sh[t - off] : 0;
        __syncthreads();
        sh[t] += add;
        __syncthreads();
    }
    if (idx < N) g_rowstart[idx] = sh[t];          // per-block inclusive (temp)
    if (t == 1023) g_blocksums[blockIdx.x] = sh[1023];
}

// Fused: every block redundantly scans the (<=128) block sums in smem, then
// converts to exclusive row starts and RESETS g_deg for the next replay.
__global__ void k_scan_finish(int N, int TOT, int nb) {
    __shared__ int soff[128];
    int t = threadIdx.x;    // blockDim == 256
    if (t < 128) soff[t] = (t < nb) ? g_blocksums[t] : 0;
    __syncthreads();
    #pragma unroll
    for (int off = 1; off < 128; off <<= 1) {
        int add = 0;
        if (t < 128 && t >= off) add = soff[t - off];
        __syncthreads();
        if (t < 128) soff[t] += add;
        __syncthreads();
    }
    int idx = blockIdx.x * blockDim.x + t;
    if (idx < N) {
        int b = idx >> 10;
        int boff = (b == 0) ? 0 : soff[b - 1];
        int incl = g_rowstart[idx] + boff;
        g_rowstart[idx] = incl - (g_deg[idx] + 1);
        g_deg[idx] = 0;       // reset for next replay
    }
    if (idx == 0) g_rowstart[N] = TOT;
}

// Atomic-free scatter: pos = rowstart[d] + rank; self-loop at rowstart[n+1]-1.
__global__ void k_scatter(const int* __restrict__ src, const int* __restrict__ dst,
                          int E, int N) {
    int base = blockIdx.x * 1024 + threadIdx.x;
    #pragma unroll
    for (int k = 0; k < 4; k++) {
        int i = base + k * 256;
        if (i < E) {
            int d = dst[i];
            g_csrsrc[g_rowstart[d] + g_rank[i]] = src[i];
        } else if (i < E + N) {
            int n = i - E;
            g_csrsrc[g_rowstart[n + 1] - 1] = n;  // self loop
        }
    }
}

// ---------------- node transform: h = y @ W^T, attention logits ----------------
// Block = 128 threads handling 256 nodes (2 per thread). Rows staged coalesced
// into padded smem (stride 37, odd -> conflict-free); h written back through
// the same rows and stored coalesced to dense rows.
template <int IN, bool FROMX>
__global__ void __launch_bounds__(128) k_node_transform(
        const float* __restrict__ xin,
        const float* __restrict__ W,
        const float* __restrict__ asrc,
        const float* __restrict__ adst, int N) {
    __shared__ float sW[F * F];
    __shared__ float sA[F], sB[F];
    __shared__ float sy[256 * 37];
    int t = threadIdx.x;
    for (int i = t; i < F * IN; i += 128) sW[i] = W[i];
    if (t < F) { sA[t] = asrc[t]; sB[t] = adst[t]; }

    int n0 = blockIdx.x * 256;
    int rows = min(256, N - n0);
    const float* srcbase = FROMX ? (xin + (size_t)n0 * IN) : (g_y + (size_t)n0 * IN);
    int avail = rows * IN;
    for (int idx = t; idx < avail; idx += 128) {
        int r = idx / IN, c = idx - r * IN;
        sy[r * 37 + c] = srcbase[idx];
    }
    __syncthreads();

    bool va = (t < rows);
    bool vb = (t + 128 < rows);
    int na = n0 + t, nb2 = n0 + t + 128;
    float ya[IN], yb[IN];
    #pragma unroll
    for (int i = 0; i < IN; i++) ya[i] = va ? sy[t * 37 + i] : 0.f;
    #pragma unroll
    for (int i = 0; i < IN; i++) yb[i] = vb ? sy[(t + 128) * 37 + i] : 0.f;

    float asa[3] = {0.f, 0.f, 0.f}, ada[3] = {0.f, 0.f, 0.f};
    float asb[3] = {0.f, 0.f, 0.f}, adb[3] = {0.f, 0.f, 0.f};

    #pragma unroll
    for (int j = 0; j < F; j++) {
        float ha = 0.f, hb = 0.f;
        #pragma unroll
        for (int i = 0; i < IN; i++) {
            float w = sW[j * IN + i];
            ha += w * ya[i];
            hb += w * yb[i];
        }
        sy[t * 37 + j] = ha;            // own row: no cross-thread hazard
        sy[(t + 128) * 37 + j] = hb;
        float aj = sA[j], bj = sB[j];
        int hh = j / OUTF;
        asa[hh] += ha * aj; ada[hh] += ha * bj;
        asb[hh] += hb * aj; adb[hh] += hb * bj;
    }
    if (va) {
        #pragma unroll
        for (int hh = 0; hh < 3; hh++) {
            g_als[na * 3 + hh] = asa[hh];
            g_ald[na * 3 + hh] = ada[hh];
        }
    }
    if (vb) {
        #pragma unroll
        for (int hh = 0; hh < 3; hh++) {
            g_als[nb2 * 3 + hh] = asb[hh];
            g_ald[nb2 * 3 + hh] = adb[hh];
        }
    }
    __syncthreads();
    int availh = rows * F;
    float* hbase = g_h + (size_t)n0 * F;
    for (int idx = t; idx < availh; idx += 128) {
        int r = idx / F, c = idx - r * F;
        hbase[idx] = sy[r * 37 + c];
    }
}

// ---------------- aggregation: warp per node, FEATURE per lane ----------------
// Lane f (0..31) owns feature f; lanes 24..27 additionally own features 32..35
// (same head 2 -> reuse own p and sp; no per-edge shuffle). The softmax
// denominator is accumulated identically by every lane of a head group.
template <bool CONCAT>
__global__ void k_gat_aggregate(const float* __restrict__ bias, int N) {
    int warp = (blockIdx.x * blockDim.x + threadIdx.x) >> 5;
    int lane = threadIdx.x & 31;
    if (warp >= N) return;
    int n = warp;
    int r0 = g_rowstart[n];
    int r1 = g_rowstart[n + 1];

    int h1 = lane / OUTF;          // 0,1,2
    float ald1 = g_ald[n * 3 + h1];
    bool sec = (lane >= 24) && (lane < 28);

    float acc1 = 0.f, acc2 = 0.f, sp1 = 0.f;

    for (int base = r0; base < r1; base += 32) {
        int mysrc = g_csrsrc[base + lane];   // chunk preload (zero-padded tail)
        int cnt = min(32, r1 - base);
        #pragma unroll 4
        for (int j = 0; j < cnt; j++) {
            int s = __shfl_sync(0xFFFFFFFFu, mysrc, j);
            float e = g_als[s * 3 + h1] + ald1;
            e = fmaxf(e, 0.2f * e);          // leaky relu (slope < 1)
            float p = __expf(e);
            sp1 += p;
            const float* hr = g_h + (size_t)s * F;
            acc1 += p * hr[lane];
            if (sec) acc2 += p * hr[32 + (lane - 24)];
        }
    }

    float inv1 = 1.f / (sp1 + 1e-16f);

    if (CONCAT) {
        float v = acc1 * inv1 + bias[lane];
        g_y[(size_t)n * F + lane] = fmaxf(v, 0.f);
        if (sec) {
            float v2 = acc2 * inv1 + bias[32 + (lane - 24)];
            g_y[(size_t)n * F + 32 + (lane - 24)] = fmaxf(v2, 0.f);
        }
    } else {
        // mean over heads
        float v1 = acc1 * inv1;              // (head h1, feat lane%12)
        float v2 = acc2 * inv1;              // lanes 24..27: head2 feats 8..11
        float b12 = __shfl_sync(0xFFFFFFFFu, v1, lane + 12);           // head1
        float c24 = __shfl_sync(0xFFFFFFFFu, v1, lane + 24);           // head2 o<8
        float c2  = __shfl_sync(0xFFFFFFFFu, v2, lane + 16);           // head2 o>=8
        if (lane < OUTF) {
            float c = (lane < 8) ? c24 : c2;
            float v = (v1 + b12 + c) * (1.f / 3.f) + bias[lane];
            g_y[(size_t)n * OUTF + lane] = v;   // no relu on last GAT layer
        }
    }
}

// ---------------- final linears: [N,12] -> 12 -> 6 ----------------
__global__ void k_final_linear(const float* __restrict__ w1, const float* __restrict__ b1,
                               const float* __restrict__ w2, const float* __restrict__ b2,
                               float* __restrict__ out, int N) {
    __shared__ float sw1[144], sb1[12], sw2[72], sb2[6];
    int t = threadIdx.x;
    for (int i = t; i < 144; i += blockDim.x) sw1[i] = w1[i];
    for (int i = t; i < 72;  i += blockDim.x) sw2[i] = w2[i];
    if (t < 12) sb1[t] = b1[t];
    if (t < 6)  sb2[t] = b2[t];
    __syncthreads();
    int n = blockIdx.x * blockDim.x + t;
    if (n >= N) return;
    float v[12];
    const float4* vp = (const float4*)(g_y + (size_t)n * 12);
    #pragma unroll
    for (int q = 0; q < 3; q++) {
        float4 w = vp[q];
        v[q * 4 + 0] = w.x; v[q * 4 + 1] = w.y;
        v[q * 4 + 2] = w.z; v[q * 4 + 3] = w.w;
    }
    float u[12];
    #pragma unroll
    for (int j = 0; j < 12; j++) {
        float a = sb1[j];
        #pragma unroll
        for (int i = 0; i < 12; i++) a += v[i] * sw1[j * 12 + i];
        u[j] = a;
    }
    #pragma unroll
    for (int k = 0; k < 6; k++) {
        float a = sb2[k];
        #pragma unroll
        for (int j = 0; j < 12; j++) a += u[j] * sw2[k * 12 + j];
        out[(size_t)n * 6 + k] = a;
    }
}

// ---------------- launch ----------------
extern "C" void kernel_launch(void* const* d_in, const int* in_sizes, int n_in,
                              void* d_out, int out_size) {
    const float* x  = (const float*)d_in[0];
    const int*   ei = (const int*)d_in[1];
    int E = in_sizes[1] / 2;
    int N = in_sizes[0] / 24;
    if (N > NMAX || E > EMAX) return;
    const int* srcp = ei;
    const int* dstp = ei + E;

    const float* W[4], *AS[4], *AD[4], *B[4];
    for (int l = 0; l < 4; l++) {
        W[l]  = (const float*)d_in[2 + 4 * l];
        AS[l] = (const float*)d_in[3 + 4 * l];
        AD[l] = (const float*)d_in[4 + 4 * l];
        B[l]  = (const float*)d_in[5 + 4 * l];
    }
    const float* lin1w = (const float*)d_in[18];
    const float* lin1b = (const float*)d_in[19];
    const float* lin2w = (const float*)d_in[20];
    const float* lin2b = (const float*)d_in[21];
    float* out = (float*)d_out;

    int TOT = E + N;
    int nb = (N + 1023) / 1024;

    k_hist<<<(E + 1023) / 1024, 256>>>(dstp, E);
    k_scan_block<<<nb, 1024>>>(N);
    k_scan_finish<<<(N + 255) / 256, 256>>>(N, TOT, nb);
    k_scatter<<<(TOT + 1023) / 1024, 256>>>(srcp, dstp, E, N);

    int ngrid = (N + 255) / 256;             // 256 nodes per transform block
    int agrid = (N * 32 + 255) / 256;        // 1 node per warp

    // layer 0 (in=24, from x)
    k_node_transform<24, true><<<ngrid, 128>>>(x, W[0], AS[0], AD[0], N);
    k_gat_aggregate<true><<<agrid, 256>>>(B[0], N);
    // layer 1
    k_node_transform<36, false><<<ngrid, 128>>>(nullptr, W[1], AS[1], AD[1], N);
    k_gat_aggregate<true><<<agrid, 256>>>(B[1], N);
    // layer 2
    k_node_transform<36, false><<<ngrid, 128>>>(nullptr, W[2], AS[2], AD[2], N);
    k_gat_aggregate<true><<<agrid, 256>>>(B[2], N);
    // layer 3 (mean over heads, no relu)
    k_node_transform<36, false><<<ngrid, 128>>>(nullptr, W[3], AS[3], AD[3], N);
    k_gat_aggregate<false><<<agrid, 256>>>(B[3], N);

    k_final_linear<<<(N + 127) / 128, 128>>>(lin1w, lin1b, lin2w, lin2b, out, N);
}